// round 1
// baseline (speedup 1.0000x reference)
#include <cuda_runtime.h>
#include <math_constants.h>

#define N_SPAT 8000
#define CIN 64
#define DQK 8
#define DV 64
#define LOG2E_F 1.4426950408889634f

// ---------------- scratch (no allocations allowed) ----------------
__device__ float g_Q[2 * N_SPAT * DQK];   // [b][i][c8]
__device__ float g_K[2 * N_SPAT * DQK];   // [b][j][c8]
__device__ float g_V[2 * N_SPAT * DV];    // [b][j][c64]

// ---------------- f32x2 helpers (FFMA2 path, sm_10x) ----------------
__device__ __forceinline__ unsigned long long dup2(float x) {
    unsigned long long r;
    asm("mov.b64 %0, {%1, %1};" : "=l"(r) : "r"(__float_as_uint(x)));
    return r;
}
__device__ __forceinline__ unsigned long long pack2(float lo, float hi) {
    unsigned long long r;
    asm("mov.b64 %0, {%1, %2};" : "=l"(r) : "r"(__float_as_uint(lo)), "r"(__float_as_uint(hi)));
    return r;
}
__device__ __forceinline__ void fma2(unsigned long long& d, unsigned long long a, unsigned long long b) {
    asm("fma.rn.f32x2 %0, %1, %2, %0;" : "+l"(d) : "l"(a), "l"(b));
}
__device__ __forceinline__ unsigned long long mul2(unsigned long long a, unsigned long long b) {
    unsigned long long r;
    asm("mul.rn.f32x2 %0, %1, %2;" : "=l"(r) : "l"(a), "l"(b));
    return r;
}
__device__ __forceinline__ float lo32(unsigned long long v) { return __uint_as_float((unsigned)v); }
__device__ __forceinline__ float hi32(unsigned long long v) { return __uint_as_float((unsigned)(v >> 32)); }

// ---------------- cp.async helpers ----------------
__device__ __forceinline__ void cp_async16(void* smem, const void* gmem) {
    unsigned saddr = (unsigned)__cvta_generic_to_shared(smem);
    asm volatile("cp.async.cg.shared.global [%0], [%1], 16;\n" :: "r"(saddr), "l"(gmem));
}
__device__ __forceinline__ void cp_commit() { asm volatile("cp.async.commit_group;\n"); }
__device__ __forceinline__ void cp_wait0() { asm volatile("cp.async.wait_group 0;\n"); }

// =====================================================================
// Conv kernel: fused Q/K/V 3x3x3 SAME conv.
// Grid (5 ocGroups, 20 z, 2 b), block 400 (one thread per (y,x)).
// ocGroup 0 -> Q(0..7)+K(0..7); groups 1..4 -> V channels 16*(g-1)..+15.
// Inner loop: f32x2 FMA over oc pairs (weights pair-contiguous in smem).
// =====================================================================
#define CONV_T 400
#define ICCHUNK 4

__global__ __launch_bounds__(CONV_T) void conv_qkv_kernel(
    const float* __restrict__ x,
    const float* __restrict__ wq, const float* __restrict__ bq,
    const float* __restrict__ wk, const float* __restrict__ bk,
    const float* __restrict__ wv, const float* __restrict__ bv)
{
    __shared__ __align__(16) float slab[ICCHUNK][3][400];
    __shared__ __align__(16) float wsm[ICCHUNK][27][16];

    const int g = blockIdx.x;
    const int z = blockIdx.y;
    const int b = blockIdx.z;
    const int tid = threadIdx.x;           // 0..399 == spatial (y,x)
    const int y = tid / 20;
    const int xc = tid % 20;
    const int ocbase = g * 16;

    unsigned long long acc[8];
#pragma unroll
    for (int o2 = 0; o2 < 8; ++o2) {
        int oc0 = ocbase + 2 * o2, oc1 = oc0 + 1;
        float b0 = (oc0 < 8) ? bq[oc0] : (oc0 < 16 ? bk[oc0 - 8] : bv[oc0 - 16]);
        float b1 = (oc1 < 8) ? bq[oc1] : (oc1 < 16 ? bk[oc1 - 8] : bv[oc1 - 16]);
        acc[o2] = pack2(b0, b1);
    }

    for (int chunk = 0; chunk < CIN / ICCHUNK; ++chunk) {
        __syncthreads();
        // fill input slab (with z zero-padding)
        for (int idx = tid; idx < ICCHUNK * 3 * 400; idx += CONV_T) {
            int spl = idx % 400;
            int zz = (idx / 400) % 3;
            int ic = idx / 1200;
            int zg = z + zz - 1;
            float v = 0.f;
            if ((unsigned)zg < 20u)
                v = x[(((size_t)b * 64 + chunk * ICCHUNK + ic) * 20 + zg) * 400 + spl];
            slab[ic][zz][spl] = v;
        }
        // fill weights [ic][tap][ocl]  (oc pairs contiguous for f32x2)
        for (int idx = tid; idx < ICCHUNK * 27 * 16; idx += CONV_T) {
            int ocl = idx & 15;
            int tap = (idx >> 4) % 27;
            int ic = idx / (27 * 16);
            int oc = ocbase + ocl;
            int icg = chunk * ICCHUNK + ic;
            float w;
            if (oc < 8)       w = wq[((size_t)oc * 64 + icg) * 27 + tap];
            else if (oc < 16) w = wk[((size_t)(oc - 8) * 64 + icg) * 27 + tap];
            else              w = wv[((size_t)(oc - 16) * 64 + icg) * 27 + tap];
            wsm[ic][tap][ocl] = w;
        }
        __syncthreads();

#pragma unroll
        for (int ic = 0; ic < ICCHUNK; ++ic) {
#pragma unroll
            for (int dz = 0; dz < 3; ++dz) {
#pragma unroll
                for (int dy = 0; dy < 3; ++dy) {
                    int yy = y + dy - 1;
                    bool yok = ((unsigned)yy < 20u);
#pragma unroll
                    for (int dx = 0; dx < 3; ++dx) {
                        int xx = xc + dx - 1;
                        bool ok = yok && ((unsigned)xx < 20u);
                        int off = ok ? (yy * 20 + xx) : 0;
                        float xv = slab[ic][dz][off];
                        xv = ok ? xv : 0.f;
                        unsigned long long xd = dup2(xv);
                        const unsigned long long* wp =
                            (const unsigned long long*)&wsm[ic][(dz * 3 + dy) * 3 + dx][0];
#pragma unroll
                        for (int o2 = 0; o2 < 8; ++o2) fma2(acc[o2], wp[o2], xd);
                    }
                }
            }
        }
    }

    // write out transposed layouts for attention
    const int i = z * 400 + tid;
#pragma unroll
    for (int o2 = 0; o2 < 8; ++o2) {
        float v0 = lo32(acc[o2]), v1 = hi32(acc[o2]);
        int oc0 = ocbase + 2 * o2;
#pragma unroll
        for (int h = 0; h < 2; ++h) {
            int oc = oc0 + h;
            float v = h ? v1 : v0;
            if (oc < 8)       g_Q[((size_t)b * N_SPAT + i) * DQK + oc] = v;
            else if (oc < 16) g_K[((size_t)b * N_SPAT + i) * DQK + (oc - 8)] = v;
            else              g_V[((size_t)b * N_SPAT + i) * DV + (oc - 16)] = v;
        }
    }
}

// =====================================================================
// Flash attention kernel.
// BM=128 rows/CTA, BN=64 cols/tile, 128 threads (tr=tid>>3 rows 8tr..,
// tc=tid&7 -> 8 j-cols in phase A / 8 c-cols in phase C).
// Phase A scalar FFMA (k=8), softmax via MUFU exp2 + octet shuffles,
// Phase C: P broadcast by warp shuffle, f32x2 FMA into 8x8 O micro-tile.
// K/V double-buffered (K via LDG->STS transpose, V via cp.async).
// =====================================================================
#define BM 128
#define BN 64
#define ATT_T 128

__global__ __launch_bounds__(ATT_T, 1) void attn_kernel(float* __restrict__ out)
{
    __shared__ __align__(16) float sQT[DQK][BM];       // Q^T, pre-scaled by log2(e)
    __shared__ __align__(16) float sKT[2][DQK][BN];    // K^T per buffer
    __shared__ __align__(16) float sV[2][BN][DV];      // V rows per buffer

    const int b = blockIdx.y;
    const int i0 = blockIdx.x * BM;
    const int tid = threadIdx.x;
    const int tc = tid & 7;
    const int tr = tid >> 3;
    const int lane = tid & 31;

    const float* Qb = g_Q + (size_t)b * N_SPAT * DQK;
    const float* Kb = g_K + (size_t)b * N_SPAT * DQK;
    const float* Vb = g_V + (size_t)b * N_SPAT * DV;

    // ---- load Q tile, transpose, pre-scale by log2(e) ----
    {
        int i = i0 + tid;
        float4 q0 = make_float4(0.f, 0.f, 0.f, 0.f), q1 = q0;
        if (i < N_SPAT) {
            const float4* qp = (const float4*)(Qb + (size_t)i * DQK);
            q0 = qp[0]; q1 = qp[1];
        }
        sQT[0][tid] = q0.x * LOG2E_F; sQT[1][tid] = q0.y * LOG2E_F;
        sQT[2][tid] = q0.z * LOG2E_F; sQT[3][tid] = q0.w * LOG2E_F;
        sQT[4][tid] = q1.x * LOG2E_F; sQT[5][tid] = q1.y * LOG2E_F;
        sQT[6][tid] = q1.z * LOG2E_F; sQT[7][tid] = q1.w * LOG2E_F;
    }

    float m[8], l[8];
    unsigned long long o[8][4];
#pragma unroll
    for (int ii = 0; ii < 8; ++ii) {
        m[ii] = -CUDART_INF_F;
        l[ii] = 0.f;
#pragma unroll
        for (int c2 = 0; c2 < 4; ++c2) o[ii][c2] = 0ull;
    }

    const int NT = N_SPAT / BN;   // 125, exact

    // ---- prologue: stage tile 0 into buffer 0 ----
    {
        float4 kreg = ((const float4*)Kb)[tid];
        const float* vsrc = Vb;
#pragma unroll
        for (int q = 0; q < 8; ++q)
            cp_async16(&((float*)sV[0])[(tid + q * 128) * 4], vsrc + (size_t)(tid + q * 128) * 4);
        cp_commit();
        int j = tid >> 1, k0 = (tid & 1) * 4;
        sKT[0][k0 + 0][j] = kreg.x; sKT[0][k0 + 1][j] = kreg.y;
        sKT[0][k0 + 2][j] = kreg.z; sKT[0][k0 + 3][j] = kreg.w;
        cp_wait0();
        __syncthreads();
    }

    for (int it = 0; it < NT; ++it) {
        const int cur = it & 1;
        const int nxt = cur ^ 1;
        const bool pref = (it + 1 < NT);
        float4 kreg;
        if (pref) {
            int j0n = (it + 1) * BN;
            kreg = ((const float4*)(Kb + (size_t)j0n * DQK))[tid];
            const float* vsrc = Vb + (size_t)j0n * DV;
#pragma unroll
            for (int q = 0; q < 8; ++q)
                cp_async16(&((float*)sV[nxt])[(tid + q * 128) * 4], vsrc + (size_t)(tid + q * 128) * 4);
            cp_commit();
        }

        // ---- phase A: S = Q K^T (8x8 micro-tile, k=8) ----
        float s[8][8];
#pragma unroll
        for (int ii = 0; ii < 8; ++ii)
#pragma unroll
            for (int jj = 0; jj < 8; ++jj) s[ii][jj] = 0.f;

#pragma unroll
        for (int k = 0; k < DQK; ++k) {
            float4 qa = *(const float4*)&sQT[k][8 * tr];
            float4 qb = *(const float4*)&sQT[k][8 * tr + 4];
            float4 ka = *(const float4*)&sKT[cur][k][8 * tc];
            float4 kb = *(const float4*)&sKT[cur][k][8 * tc + 4];
            float qv[8] = {qa.x, qa.y, qa.z, qa.w, qb.x, qb.y, qb.z, qb.w};
            float kv[8] = {ka.x, ka.y, ka.z, ka.w, kb.x, kb.y, kb.z, kb.w};
#pragma unroll
            for (int ii = 0; ii < 8; ++ii)
#pragma unroll
                for (int jj = 0; jj < 8; ++jj)
                    s[ii][jj] = fmaf(qv[ii], kv[jj], s[ii][jj]);
        }

        // ---- online softmax (base-2 domain; Q was pre-scaled) ----
#pragma unroll
        for (int ii = 0; ii < 8; ++ii) {
            float mx = s[ii][0];
#pragma unroll
            for (int jj = 1; jj < 8; ++jj) mx = fmaxf(mx, s[ii][jj]);
            mx = fmaxf(mx, __shfl_xor_sync(0xffffffffu, mx, 1));
            mx = fmaxf(mx, __shfl_xor_sync(0xffffffffu, mx, 2));
            mx = fmaxf(mx, __shfl_xor_sync(0xffffffffu, mx, 4));
            float mnew = fmaxf(m[ii], mx);
            float alpha = exp2f(m[ii] - mnew);
            m[ii] = mnew;
            float rs = 0.f;
#pragma unroll
            for (int jj = 0; jj < 8; ++jj) {
                float p = exp2f(s[ii][jj] - mnew);
                s[ii][jj] = p;          // s now holds P
                rs += p;
            }
            rs += __shfl_xor_sync(0xffffffffu, rs, 1);
            rs += __shfl_xor_sync(0xffffffffu, rs, 2);
            rs += __shfl_xor_sync(0xffffffffu, rs, 4);
            l[ii] = l[ii] * alpha + rs;
            unsigned long long a2 = dup2(alpha);
#pragma unroll
            for (int c2 = 0; c2 < 4; ++c2) o[ii][c2] = mul2(o[ii][c2], a2);
        }

        // ---- phase C: O += P @ V  (P broadcast via shuffle, FFMA2) ----
#pragma unroll
        for (int ko = 0; ko < 8; ++ko) {
#pragma unroll
            for (int jj = 0; jj < 8; ++jj) {
                int k = ko * 8 + jj;
                const ulonglong2* vp = (const ulonglong2*)&sV[cur][k][8 * tc];
                ulonglong2 v01 = vp[0];
                ulonglong2 v23 = vp[1];
                int srcLane = (lane & 24) | ko;
#pragma unroll
                for (int ii = 0; ii < 8; ++ii) {
                    float pv = __shfl_sync(0xffffffffu, s[ii][jj], srcLane);
                    unsigned long long pd = dup2(pv);
                    fma2(o[ii][0], v01.x, pd);
                    fma2(o[ii][1], v01.y, pd);
                    fma2(o[ii][2], v23.x, pd);
                    fma2(o[ii][3], v23.y, pd);
                }
            }
        }

        if (pref) {
            int j = tid >> 1, k0 = (tid & 1) * 4;
            sKT[nxt][k0 + 0][j] = kreg.x; sKT[nxt][k0 + 1][j] = kreg.y;
            sKT[nxt][k0 + 2][j] = kreg.z; sKT[nxt][k0 + 3][j] = kreg.w;
        }
        cp_wait0();
        __syncthreads();
    }

    // ---- epilogue: normalize, write out[b][c][i] ----
#pragma unroll
    for (int ii = 0; ii < 8; ++ii) {
        int i = i0 + 8 * tr + ii;
        if (i < N_SPAT) {
            float inv = 1.0f / l[ii];
#pragma unroll
            for (int c2 = 0; c2 < 4; ++c2) {
                float vlo = lo32(o[ii][c2]) * inv;
                float vhi = hi32(o[ii][c2]) * inv;
                int c = 8 * tc + 2 * c2;
                out[((size_t)b * DV + c) * N_SPAT + i] = vlo;
                out[((size_t)b * DV + c + 1) * N_SPAT + i] = vhi;
            }
        }
    }
}

// =====================================================================
extern "C" void kernel_launch(void* const* d_in, const int* in_sizes, int n_in,
                              void* d_out, int out_size)
{
    const float* x  = (const float*)d_in[0];
    const float* wq = (const float*)d_in[1];
    const float* bq = (const float*)d_in[2];
    const float* wk = (const float*)d_in[3];
    const float* bk = (const float*)d_in[4];
    const float* wv = (const float*)d_in[5];
    const float* bv = (const float*)d_in[6];
    float* out = (float*)d_out;

    dim3 cgrid(5, 20, 2);                 // ocGroup, z, batch
    conv_qkv_kernel<<<cgrid, CONV_T>>>(x, wq, bq, wk, bk, wv, bv);

    dim3 agrid((N_SPAT + BM - 1) / BM, 2);  // 63 x 2
    attn_kernel<<<agrid, ATT_T>>>(out);
}

// round 2
// speedup vs baseline: 1.0009x; 1.0009x over previous
#include <cuda_runtime.h>
#include <math_constants.h>

#define N_SPAT 8000
#define CIN 64
#define DQK 8
#define DV 64
#define LOG2E_F 1.4426950408889634f

// ---------------- scratch (no allocations allowed) ----------------
__device__ float g_Q[2 * N_SPAT * DQK];   // [b][i][c8]
__device__ float g_K[2 * N_SPAT * DQK];   // [b][j][c8]
__device__ float g_V[2 * N_SPAT * DV];    // [b][j][c64]

// ---------------- f32x2 helpers (FFMA2 path, sm_10x) ----------------
__device__ __forceinline__ unsigned long long dup2(float x) {
    unsigned long long r;
    asm("mov.b64 %0, {%1, %1};" : "=l"(r) : "r"(__float_as_uint(x)));
    return r;
}
__device__ __forceinline__ unsigned long long pack2(float lo, float hi) {
    unsigned long long r;
    asm("mov.b64 %0, {%1, %2};" : "=l"(r) : "r"(__float_as_uint(lo)), "r"(__float_as_uint(hi)));
    return r;
}
__device__ __forceinline__ void fma2(unsigned long long& d, unsigned long long a, unsigned long long b) {
    asm("fma.rn.f32x2 %0, %1, %2, %0;" : "+l"(d) : "l"(a), "l"(b));
}
__device__ __forceinline__ unsigned long long mul2(unsigned long long a, unsigned long long b) {
    unsigned long long r;
    asm("mul.rn.f32x2 %0, %1, %2;" : "=l"(r) : "l"(a), "l"(b));
    return r;
}
__device__ __forceinline__ float lo32(unsigned long long v) { return __uint_as_float((unsigned)v); }
__device__ __forceinline__ float hi32(unsigned long long v) { return __uint_as_float((unsigned)(v >> 32)); }

// ---------------- cp.async helpers ----------------
__device__ __forceinline__ void cp_async16(void* smem, const void* gmem) {
    unsigned saddr = (unsigned)__cvta_generic_to_shared(smem);
    asm volatile("cp.async.cg.shared.global [%0], [%1], 16;\n" :: "r"(saddr), "l"(gmem));
}
__device__ __forceinline__ void cp_commit() { asm volatile("cp.async.commit_group;\n"); }
__device__ __forceinline__ void cp_wait0() { asm volatile("cp.async.wait_group 0;\n"); }

// =====================================================================
// Conv kernel: fused Q/K/V 3x3x3 SAME conv.
// Grid (5 ocGroups, 20 z, 2 b), block 400 (one thread per (y,x)).
// ocGroup 0 -> Q(0..7)+K(0..7); groups 1..4 -> V channels 16*(g-1)..+15.
// Inner loop: f32x2 FMA over oc pairs (weights pair-contiguous in smem).
// =====================================================================
#define CONV_T 400
#define ICCHUNK 4

__global__ __launch_bounds__(CONV_T) void conv_qkv_kernel(
    const float* __restrict__ x,
    const float* __restrict__ wq, const float* __restrict__ bq,
    const float* __restrict__ wk, const float* __restrict__ bk,
    const float* __restrict__ wv, const float* __restrict__ bv)
{
    __shared__ __align__(16) float slab[ICCHUNK][3][400];
    __shared__ __align__(16) float wsm[ICCHUNK][27][16];

    const int g = blockIdx.x;
    const int z = blockIdx.y;
    const int b = blockIdx.z;
    const int tid = threadIdx.x;           // 0..399 == spatial (y,x)
    const int y = tid / 20;
    const int xc = tid % 20;
    const int ocbase = g * 16;

    unsigned long long acc[8];
#pragma unroll
    for (int o2 = 0; o2 < 8; ++o2) {
        int oc0 = ocbase + 2 * o2, oc1 = oc0 + 1;
        float b0 = (oc0 < 8) ? bq[oc0] : (oc0 < 16 ? bk[oc0 - 8] : bv[oc0 - 16]);
        float b1 = (oc1 < 8) ? bq[oc1] : (oc1 < 16 ? bk[oc1 - 8] : bv[oc1 - 16]);
        acc[o2] = pack2(b0, b1);
    }

    for (int chunk = 0; chunk < CIN / ICCHUNK; ++chunk) {
        __syncthreads();
        // fill input slab (with z zero-padding)
        for (int idx = tid; idx < ICCHUNK * 3 * 400; idx += CONV_T) {
            int spl = idx % 400;
            int zz = (idx / 400) % 3;
            int ic = idx / 1200;
            int zg = z + zz - 1;
            float v = 0.f;
            if ((unsigned)zg < 20u)
                v = x[(((size_t)b * 64 + chunk * ICCHUNK + ic) * 20 + zg) * 400 + spl];
            slab[ic][zz][spl] = v;
        }
        // fill weights [ic][tap][ocl]  (oc pairs contiguous for f32x2)
        for (int idx = tid; idx < ICCHUNK * 27 * 16; idx += CONV_T) {
            int ocl = idx & 15;
            int tap = (idx >> 4) % 27;
            int ic = idx / (27 * 16);
            int oc = ocbase + ocl;
            int icg = chunk * ICCHUNK + ic;
            float w;
            if (oc < 8)       w = wq[((size_t)oc * 64 + icg) * 27 + tap];
            else if (oc < 16) w = wk[((size_t)(oc - 8) * 64 + icg) * 27 + tap];
            else              w = wv[((size_t)(oc - 16) * 64 + icg) * 27 + tap];
            wsm[ic][tap][ocl] = w;
        }
        __syncthreads();

#pragma unroll
        for (int ic = 0; ic < ICCHUNK; ++ic) {
#pragma unroll
            for (int dz = 0; dz < 3; ++dz) {
#pragma unroll
                for (int dy = 0; dy < 3; ++dy) {
                    int yy = y + dy - 1;
                    bool yok = ((unsigned)yy < 20u);
#pragma unroll
                    for (int dx = 0; dx < 3; ++dx) {
                        int xx = xc + dx - 1;
                        bool ok = yok && ((unsigned)xx < 20u);
                        int off = ok ? (yy * 20 + xx) : 0;
                        float xv = slab[ic][dz][off];
                        xv = ok ? xv : 0.f;
                        unsigned long long xd = dup2(xv);
                        const unsigned long long* wp =
                            (const unsigned long long*)&wsm[ic][(dz * 3 + dy) * 3 + dx][0];
#pragma unroll
                        for (int o2 = 0; o2 < 8; ++o2) fma2(acc[o2], wp[o2], xd);
                    }
                }
            }
        }
    }

    // write out transposed layouts for attention
    const int i = z * 400 + tid;
#pragma unroll
    for (int o2 = 0; o2 < 8; ++o2) {
        float v0 = lo32(acc[o2]), v1 = hi32(acc[o2]);
        int oc0 = ocbase + 2 * o2;
#pragma unroll
        for (int h = 0; h < 2; ++h) {
            int oc = oc0 + h;
            float v = h ? v1 : v0;
            if (oc < 8)       g_Q[((size_t)b * N_SPAT + i) * DQK + oc] = v;
            else if (oc < 16) g_K[((size_t)b * N_SPAT + i) * DQK + (oc - 8)] = v;
            else              g_V[((size_t)b * N_SPAT + i) * DV + (oc - 16)] = v;
        }
    }
}

// =====================================================================
// Flash attention kernel.
// BM=128 rows/CTA, BN=64 cols/tile, 128 threads (tr=tid>>3 rows 8tr..,
// tc=tid&7 -> 8 j-cols in phase A / 8 c-cols in phase C).
// Phase A scalar FFMA (k=8), softmax via MUFU exp2 + octet shuffles,
// Phase C: P broadcast by warp shuffle, f32x2 FMA into 8x8 O micro-tile.
// K/V double-buffered (K via LDG->STS transpose, V via cp.async).
// =====================================================================
#define BM 128
#define BN 64
#define ATT_T 128

__global__ __launch_bounds__(ATT_T, 1) void attn_kernel(float* __restrict__ out)
{
    __shared__ __align__(16) float sQT[DQK][BM];       // Q^T, pre-scaled by log2(e)
    __shared__ __align__(16) float sKT[2][DQK][BN];    // K^T per buffer
    __shared__ __align__(16) float sV[2][BN][DV];      // V rows per buffer

    const int b = blockIdx.y;
    const int i0 = blockIdx.x * BM;
    const int tid = threadIdx.x;
    const int tc = tid & 7;
    const int tr = tid >> 3;
    const int lane = tid & 31;

    const float* Qb = g_Q + (size_t)b * N_SPAT * DQK;
    const float* Kb = g_K + (size_t)b * N_SPAT * DQK;
    const float* Vb = g_V + (size_t)b * N_SPAT * DV;

    // ---- load Q tile, transpose, pre-scale by log2(e) ----
    {
        int i = i0 + tid;
        float4 q0 = make_float4(0.f, 0.f, 0.f, 0.f), q1 = q0;
        if (i < N_SPAT) {
            const float4* qp = (const float4*)(Qb + (size_t)i * DQK);
            q0 = qp[0]; q1 = qp[1];
        }
        sQT[0][tid] = q0.x * LOG2E_F; sQT[1][tid] = q0.y * LOG2E_F;
        sQT[2][tid] = q0.z * LOG2E_F; sQT[3][tid] = q0.w * LOG2E_F;
        sQT[4][tid] = q1.x * LOG2E_F; sQT[5][tid] = q1.y * LOG2E_F;
        sQT[6][tid] = q1.z * LOG2E_F; sQT[7][tid] = q1.w * LOG2E_F;
    }

    float m[8], l[8];
    unsigned long long o[8][4];
#pragma unroll
    for (int ii = 0; ii < 8; ++ii) {
        m[ii] = -CUDART_INF_F;
        l[ii] = 0.f;
#pragma unroll
        for (int c2 = 0; c2 < 4; ++c2) o[ii][c2] = 0ull;
    }

    const int NT = N_SPAT / BN;   // 125, exact

    // ---- prologue: stage tile 0 into buffer 0 ----
    {
        float4 kreg = ((const float4*)Kb)[tid];
        const float* vsrc = Vb;
#pragma unroll
        for (int q = 0; q < 8; ++q)
            cp_async16(&((float*)sV[0])[(tid + q * 128) * 4], vsrc + (size_t)(tid + q * 128) * 4);
        cp_commit();
        int j = tid >> 1, k0 = (tid & 1) * 4;
        sKT[0][k0 + 0][j] = kreg.x; sKT[0][k0 + 1][j] = kreg.y;
        sKT[0][k0 + 2][j] = kreg.z; sKT[0][k0 + 3][j] = kreg.w;
        cp_wait0();
        __syncthreads();
    }

    for (int it = 0; it < NT; ++it) {
        const int cur = it & 1;
        const int nxt = cur ^ 1;
        const bool pref = (it + 1 < NT);
        float4 kreg;
        if (pref) {
            int j0n = (it + 1) * BN;
            kreg = ((const float4*)(Kb + (size_t)j0n * DQK))[tid];
            const float* vsrc = Vb + (size_t)j0n * DV;
#pragma unroll
            for (int q = 0; q < 8; ++q)
                cp_async16(&((float*)sV[nxt])[(tid + q * 128) * 4], vsrc + (size_t)(tid + q * 128) * 4);
            cp_commit();
        }

        // ---- phase A: S = Q K^T (8x8 micro-tile, k=8) ----
        float s[8][8];
#pragma unroll
        for (int ii = 0; ii < 8; ++ii)
#pragma unroll
            for (int jj = 0; jj < 8; ++jj) s[ii][jj] = 0.f;

#pragma unroll
        for (int k = 0; k < DQK; ++k) {
            float4 qa = *(const float4*)&sQT[k][8 * tr];
            float4 qb = *(const float4*)&sQT[k][8 * tr + 4];
            float4 ka = *(const float4*)&sKT[cur][k][8 * tc];
            float4 kb = *(const float4*)&sKT[cur][k][8 * tc + 4];
            float qv[8] = {qa.x, qa.y, qa.z, qa.w, qb.x, qb.y, qb.z, qb.w};
            float kv[8] = {ka.x, ka.y, ka.z, ka.w, kb.x, kb.y, kb.z, kb.w};
#pragma unroll
            for (int ii = 0; ii < 8; ++ii)
#pragma unroll
                for (int jj = 0; jj < 8; ++jj)
                    s[ii][jj] = fmaf(qv[ii], kv[jj], s[ii][jj]);
        }

        // ---- online softmax (base-2 domain; Q was pre-scaled) ----
#pragma unroll
        for (int ii = 0; ii < 8; ++ii) {
            float mx = s[ii][0];
#pragma unroll
            for (int jj = 1; jj < 8; ++jj) mx = fmaxf(mx, s[ii][jj]);
            mx = fmaxf(mx, __shfl_xor_sync(0xffffffffu, mx, 1));
            mx = fmaxf(mx, __shfl_xor_sync(0xffffffffu, mx, 2));
            mx = fmaxf(mx, __shfl_xor_sync(0xffffffffu, mx, 4));
            float mnew = fmaxf(m[ii], mx);
            float alpha = exp2f(m[ii] - mnew);
            m[ii] = mnew;
            float rs = 0.f;
#pragma unroll
            for (int jj = 0; jj < 8; ++jj) {
                float p = exp2f(s[ii][jj] - mnew);
                s[ii][jj] = p;          // s now holds P
                rs += p;
            }
            rs += __shfl_xor_sync(0xffffffffu, rs, 1);
            rs += __shfl_xor_sync(0xffffffffu, rs, 2);
            rs += __shfl_xor_sync(0xffffffffu, rs, 4);
            l[ii] = l[ii] * alpha + rs;
            unsigned long long a2 = dup2(alpha);
#pragma unroll
            for (int c2 = 0; c2 < 4; ++c2) o[ii][c2] = mul2(o[ii][c2], a2);
        }

        // ---- phase C: O += P @ V  (P broadcast via shuffle, FFMA2) ----
#pragma unroll
        for (int ko = 0; ko < 8; ++ko) {
#pragma unroll
            for (int jj = 0; jj < 8; ++jj) {
                int k = ko * 8 + jj;
                const ulonglong2* vp = (const ulonglong2*)&sV[cur][k][8 * tc];
                ulonglong2 v01 = vp[0];
                ulonglong2 v23 = vp[1];
                int srcLane = (lane & 24) | ko;
#pragma unroll
                for (int ii = 0; ii < 8; ++ii) {
                    float pv = __shfl_sync(0xffffffffu, s[ii][jj], srcLane);
                    unsigned long long pd = dup2(pv);
                    fma2(o[ii][0], v01.x, pd);
                    fma2(o[ii][1], v01.y, pd);
                    fma2(o[ii][2], v23.x, pd);
                    fma2(o[ii][3], v23.y, pd);
                }
            }
        }

        if (pref) {
            int j = tid >> 1, k0 = (tid & 1) * 4;
            sKT[nxt][k0 + 0][j] = kreg.x; sKT[nxt][k0 + 1][j] = kreg.y;
            sKT[nxt][k0 + 2][j] = kreg.z; sKT[nxt][k0 + 3][j] = kreg.w;
        }
        cp_wait0();
        __syncthreads();
    }

    // ---- epilogue: normalize, write out[b][c][i] ----
#pragma unroll
    for (int ii = 0; ii < 8; ++ii) {
        int i = i0 + 8 * tr + ii;
        if (i < N_SPAT) {
            float inv = 1.0f / l[ii];
#pragma unroll
            for (int c2 = 0; c2 < 4; ++c2) {
                float vlo = lo32(o[ii][c2]) * inv;
                float vhi = hi32(o[ii][c2]) * inv;
                int c = 8 * tc + 2 * c2;
                out[((size_t)b * DV + c) * N_SPAT + i] = vlo;
                out[((size_t)b * DV + c + 1) * N_SPAT + i] = vhi;
            }
        }
    }
}

// =====================================================================
extern "C" void kernel_launch(void* const* d_in, const int* in_sizes, int n_in,
                              void* d_out, int out_size)
{
    const float* x  = (const float*)d_in[0];
    const float* wq = (const float*)d_in[1];
    const float* bq = (const float*)d_in[2];
    const float* wk = (const float*)d_in[3];
    const float* bk = (const float*)d_in[4];
    const float* wv = (const float*)d_in[5];
    const float* bv = (const float*)d_in[6];
    float* out = (float*)d_out;

    dim3 cgrid(5, 20, 2);                 // ocGroup, z, batch
    conv_qkv_kernel<<<cgrid, CONV_T>>>(x, wq, bq, wk, bk, wv, bv);

    dim3 agrid((N_SPAT + BM - 1) / BM, 2);  // 63 x 2
    attn_kernel<<<agrid, ATT_T>>>(out);
}